// round 7
// baseline (speedup 1.0000x reference)
#include <cuda_runtime.h>
#include <cuda_bf16.h>
#include <math.h>
#include <cstdint>

// Problem constants
#define BATCH 2
#define SEQ   2048
#define HID   4096
#define NH    32
#define NKV   8
#define HD    128
#define TOKENS (BATCH*SEQ)          // 4096
#define QROW (NH*HD)                // 4096
#define KROW (NKV*HD)               // 1024
#define QKVW (QROW + 2*KROW)        // 6144
#define VCOL0 (QROW + KROW)         // 5120 : first V column in fused qkv

// ---------------- scratch (no cudaMalloc allowed) ----------------
__device__ float g_qkv[(size_t)TOKENS * QKVW];     // q|k rows (v region unused)
__device__ float g_vt[(size_t)BATCH * NKV * HD * SEQ]; // V dim-major [b*8+kvh][d][s]
__device__ float g_attn[(size_t)TOKENS * QROW];
__device__ float g_hsc[(size_t)TOKENS * HID];
__device__ float g_wqkv[(size_t)QKVW * HID];
__device__ float g_woc[(size_t)HID * QROW];

// ---------------- helpers ----------------
__device__ __forceinline__ uint32_t sa(const void* p) {
    return (uint32_t)__cvta_generic_to_shared(p);
}
__device__ __forceinline__ void cp_async16(uint32_t s, const void* g) {
    asm volatile("cp.async.cg.shared.global [%0], [%1], 16;" :: "r"(s), "l"(g));
}
__device__ __forceinline__ void cp_commit() {
    asm volatile("cp.async.commit_group;" ::: "memory");
}
template <int N>
__device__ __forceinline__ void cp_wait() {
    asm volatile("cp.async.wait_group %0;" :: "n"(N) : "memory");
}
__device__ __forceinline__ void ldsm4(uint32_t& r0, uint32_t& r1, uint32_t& r2,
                                      uint32_t& r3, uint32_t addr) {
    asm volatile("ldmatrix.sync.aligned.m8n8.x4.shared.b16 {%0,%1,%2,%3}, [%4];"
                 : "=r"(r0), "=r"(r1), "=r"(r2), "=r"(r3) : "r"(addr));
}
__device__ __forceinline__ void mma_tf32(float* d, const uint32_t* a, const uint32_t* b) {
    asm volatile(
        "mma.sync.aligned.m16n8k8.row.col.f32.tf32.tf32.f32 "
        "{%0,%1,%2,%3}, {%4,%5,%6,%7}, {%8,%9}, {%0,%1,%2,%3};"
        : "+f"(d[0]), "+f"(d[1]), "+f"(d[2]), "+f"(d[3])
        : "r"(a[0]), "r"(a[1]), "r"(a[2]), "r"(a[3]), "r"(b[0]), "r"(b[1]));
}
__device__ __forceinline__ float tf32rn(float x) {
    uint32_t u;
    asm("cvt.rn.tf32.f32 %0, %1;" : "=r"(u) : "f"(x));
    return __uint_as_float(u);
}
__device__ __forceinline__ float ex2(float x) {
    float y;
    asm("ex2.approx.ftz.f32 %0, %1;" : "=f"(y) : "f"(x));
    return y;
}

// =================================================================
// L0: fused rounding of hs + all weights, 4 float4 per thread (MLP)
// =================================================================
#define NHS4 ((long)TOKENS * HID / 4)          // 4.19M
#define NQ4  ((long)QROW * HID / 4)
#define NK4  ((long)KROW * HID / 4)
#define NALL4 (NHS4 + NQ4 + 2*NK4 + NQ4)       // hs + wq + wk + wv + wo

__global__ __launch_bounds__(256)
void round_all_kernel(const float4* __restrict__ hs, const float4* __restrict__ wq,
                      const float4* __restrict__ wk, const float4* __restrict__ wv,
                      const float4* __restrict__ wo,
                      float4* __restrict__ hsc, float4* __restrict__ wqkv,
                      float4* __restrict__ woc)
{
    long base = ((long)blockIdx.x * 256 + threadIdx.x) * 4;
#pragma unroll
    for (int j = 0; j < 4; j++) {
        long i = base + j;
        if (i >= NALL4) return;
        float4 v;
        float4* dst;
        if (i < NHS4) { v = hs[i]; dst = hsc + i; }
        else {
            long w = i - NHS4;
            if (w < NQ4)              { v = wq[w];             dst = wqkv + w; }
            else if (w < NQ4 + NK4)   { v = wk[w - NQ4];       dst = wqkv + w; }
            else if (w < NQ4 + 2*NK4) { v = wv[w - NQ4 - NK4]; dst = wqkv + w; }
            else                      { v = wo[w - NQ4 - 2*NK4]; dst = woc + (w - NQ4 - 2*NK4); }
        }
        *dst = make_float4(tf32rn(v.x), tf32rn(v.y), tf32rn(v.z), tf32rn(v.w));
    }
}

// =================================================================
// tf32 mma.sync GEMM (ldmatrix fragments):  C[m,n] = sum_k A[m,k]*B[n,k]
// If vt != nullptr: columns >= VCOL0 are written transposed+tf32-rounded
// into vt[b*8+kvh][d][s]; other columns written normally (unrounded).
// =================================================================
#define GSTRIDE 36
#define A_FLOATS (128 * GSTRIDE)
#define B_FLOATS (256 * GSTRIDE)
#define STAGE_FLOATS (A_FLOATS + B_FLOATS)
#define GEMM_SMEM (2 * STAGE_FLOATS * 4)

__global__ __launch_bounds__(256, 1)
void gemm_mma(const float* __restrict__ A, const float* __restrict__ B,
              float* __restrict__ C, int M, int N, int K, float* __restrict__ vt)
{
    extern __shared__ float sm[];

    const int tid = threadIdx.x;
    const int wid = tid >> 5;
    const int lane = tid & 31;
    const int g = lane >> 2;
    const int t = lane & 3;
    const int lr = lane & 7;        // ldmatrix row within matrix
    const int lm = lane >> 3;       // ldmatrix matrix index 0-3
    const int wm = wid & 1;
    const int wn = wid >> 1;
    const int m0 = blockIdx.y * 128;
    const int n0 = blockIdx.x * 256;

    const float* Ag = A + (size_t)m0 * K;
    const float* Bg = B + (size_t)n0 * K;

    auto load_stage = [&](int kt, int st) {
        float* As = sm + st * STAGE_FLOATS;
        float* Bs = As + A_FLOATS;
        const float* ap = Ag + kt * 32;
        const float* bp = Bg + kt * 32;
#pragma unroll
        for (int r = 0; r < 4; r++) {
            int c = r * 256 + tid;
            int row = c >> 3;
            int c4  = (c & 7) * 4;
            cp_async16(sa(As + row * GSTRIDE + c4), ap + (size_t)row * K + c4);
        }
#pragma unroll
        for (int r = 0; r < 8; r++) {
            int c = r * 256 + tid;
            int row = c >> 3;
            int c4  = (c & 7) * 4;
            cp_async16(sa(Bs + row * GSTRIDE + c4), bp + (size_t)row * K + c4);
        }
        cp_commit();
    };

    float d[4][8][4];
#pragma unroll
    for (int mi = 0; mi < 4; mi++)
#pragma unroll
        for (int ni = 0; ni < 8; ni++)
#pragma unroll
            for (int r = 0; r < 4; r++) d[mi][ni][r] = 0.0f;

    // ldmatrix per-lane base offsets (bytes), relative to stage base
    const uint32_t aoff = (uint32_t)(((wm * 64 + (lm & 1) * 8 + lr) * GSTRIDE
                                      + (lm >> 1) * 4) * 4);
    const uint32_t boff = (uint32_t)(((wn * 64 + (lm >> 1) * 8 + lr) * GSTRIDE
                                      + (lm & 1) * 4) * 4);

    const int NT = K / 32;
    load_stage(0, 0);

    for (int kt = 0; kt < NT; kt++) {
        const int st = kt & 1;
        if (kt + 1 < NT) { load_stage(kt + 1, st ^ 1); cp_wait<1>(); }
        else             { cp_wait<0>(); }
        __syncthreads();

        const uint32_t As = sa(sm + st * STAGE_FLOATS);
        const uint32_t Bs = As + A_FLOATS * 4;

#pragma unroll
        for (int kk = 0; kk < 4; kk++) {
            uint32_t a[4][4], b[8][2];
#pragma unroll
            for (int mi = 0; mi < 4; mi++)
                ldsm4(a[mi][0], a[mi][1], a[mi][2], a[mi][3],
                      As + aoff + (uint32_t)((mi * 16 * GSTRIDE + kk * 8) * 4));
#pragma unroll
            for (int p = 0; p < 4; p++)
                ldsm4(b[2*p][0], b[2*p][1], b[2*p+1][0], b[2*p+1][1],
                      Bs + boff + (uint32_t)((p * 16 * GSTRIDE + kk * 8) * 4));
#pragma unroll
            for (int mi = 0; mi < 4; mi++)
#pragma unroll
                for (int ni = 0; ni < 8; ni++)
                    mma_tf32(d[mi][ni], a[mi], b[ni]);
        }
        __syncthreads();
    }

    // ---- epilogue ----
    const bool vmode = (vt != nullptr) && (n0 >= VCOL0);
#pragma unroll
    for (int mi = 0; mi < 4; mi++) {
        const int r0 = m0 + wm * 64 + mi * 16 + g;
        if (!vmode) {
            float* c0p = C + (size_t)r0 * N + n0 + wn * 64;
            float* c1p = c0p + (size_t)8 * N;
#pragma unroll
            for (int ni = 0; ni < 8; ni++) {
                *(float2*)(c0p + ni * 8 + t * 2) = make_float2(d[mi][ni][0], d[mi][ni][1]);
                *(float2*)(c1p + ni * 8 + t * 2) = make_float2(d[mi][ni][2], d[mi][ni][3]);
            }
        } else {
            // V columns -> vt[(b*8+kvh)*128 + d][s] ; c = global col - VCOL0
            const int tok0 = r0;
            const int tok1 = r0 + 8;
#pragma unroll
            for (int ni = 0; ni < 8; ni++) {
                int c = n0 - VCOL0 + wn * 64 + ni * 8 + 2 * t;
                float* v0 = vt + ((size_t)(tok0 >> 11) * (NKV * HD) + c) * SEQ + (tok0 & 2047);
                float* v1 = vt + ((size_t)(tok1 >> 11) * (NKV * HD) + c) * SEQ + (tok1 & 2047);
                v0[0]   = tf32rn(d[mi][ni][0]);
                v0[SEQ] = tf32rn(d[mi][ni][1]);
                v1[0]   = tf32rn(d[mi][ni][2]);
                v1[SEQ] = tf32rn(d[mi][ni][3]);
            }
        }
    }
}

// =================================================================
// L2: fused RoPE for Q (slots 0-31, scale qscale) and K (slots 32-39).
// In place on g_qkv; output tf32-rounded.
// =================================================================
__global__ __launch_bounds__(256)
void rope_qk_kernel(float* __restrict__ qkv, const float* __restrict__ cosb,
                    const float* __restrict__ sinb, float qscale)
{
    long idx = (long)blockIdx.x * blockDim.x + threadIdx.x;
    long total = (long)TOKENS * (NH + NKV) * 64;
    if (idx >= total) return;
    int d = (int)(idx & 63);
    long t2 = idx >> 6;
    int slot = (int)(t2 % (NH + NKV));
    long tok = t2 / (NH + NKV);
    float scale = (slot < NH) ? qscale : 1.0f;
    int off = (slot < NH) ? slot * HD : QROW + (slot - NH) * HD;
    float* row = qkv + tok * QKVW + off;
    float c0 = cosb[tok * HD + d];
    float s0 = sinb[tok * HD + d];
    float c1 = cosb[tok * HD + d + 64];
    float s1 = sinb[tok * HD + d + 64];
    float a = row[d];
    float b = row[d + 64];
    row[d]      = tf32rn((a * c0 - b * s0) * scale);
    row[d + 64] = tf32rn((b * c1 + a * s1) * scale);
}

// =================================================================
// L3: tensor-core flash attention (causal, GQA 4:1), tf32 mma.sync,
// ldmatrix fragments, cp.async double-buffered K/V, Q in registers.
// K from g_qkv (token stride 6144), V from g_vt (dim-major).
// CTA: 128 queries x 1 head; 8 warps x 16 query rows; key tile 64.
// =================================================================
#define AKS 132
#define AVT 68
#define APS 68
#define KS_FLOATS (64 * AKS)                  // 8448
#define VT_FLOATS (128 * AVT)                 // 8704
#define STG_FLOATS (KS_FLOATS + VT_FLOATS)    // 17152
#define PS_OFF (2 * STG_FLOATS)
#define ATTN_SMEM ((PS_OFF + 128 * APS) * 4)  // 172032 B

__global__ __launch_bounds__(256, 1)
void attn_mma(const float* __restrict__ QKV, const float* __restrict__ VT,
              float* __restrict__ O)
{
    extern __shared__ float sm[];

    const int tid = threadIdx.x;
    const int wid = tid >> 5;
    const int lane = tid & 31;
    const int g = lane >> 2;
    const int t = lane & 3;
    const int lr = lane & 7;
    const int lm = lane >> 3;

    const int bh = blockIdx.y;
    const int b   = bh >> 5;
    const int h   = bh & 31;
    const int kvh = h >> 2;
    const int qt  = (int)(gridDim.x - 1 - blockIdx.x);
    const int q0  = qt * 128;

    const float* Qb = QKV + (size_t)b * SEQ * QKVW + h * HD;
    const float* Kb = QKV + (size_t)b * SEQ * QKVW + QROW + kvh * HD;
    const float* Vg = VT + (size_t)(b * NKV + kvh) * HD * SEQ;

    // ---- stage Q into smem (stage-0 region), fragments via ldmatrix ----
    {
#pragma unroll
        for (int it = 0; it < 16; it++) {
            int idx = it * 256 + tid;
            int row = idx >> 5;
            int c4  = (idx & 31) * 4;
            cp_async16(sa(sm + row * AKS + c4),
                       Qb + (size_t)(q0 + row) * QKVW + c4);
        }
        cp_commit();
        cp_wait<0>();
        __syncthreads();
    }

    uint32_t qa[16][4];
    {
        const uint32_t qoff = sa(sm) +
            (uint32_t)(((wid * 16 + (lm & 1) * 8 + lr) * AKS + (lm >> 1) * 4) * 4);
#pragma unroll
        for (int kk = 0; kk < 16; kk++)
            ldsm4(qa[kk][0], qa[kk][1], qa[kk][2], qa[kk][3], qoff + kk * 32);
    }
    __syncthreads();

    const int qbase = q0 + wid * 16;

    float m0r = -1e30f, m1r = -1e30f, l0r = 0.0f, l1r = 0.0f;
    float oa[16][4];
#pragma unroll
    for (int ni = 0; ni < 16; ni++)
#pragma unroll
        for (int r = 0; r < 4; r++) oa[ni][r] = 0.0f;

    const int nkt = qt * 2 + 2;

    auto load_kv = [&](int kt, int st) {
        float* Ks = sm + st * STG_FLOATS;
        float* Vs = Ks + KS_FLOATS;
        const int k0 = kt * 64;
#pragma unroll
        for (int it = 0; it < 8; it++) {
            int idx = it * 256 + tid;
            int row = idx >> 5;
            int c4  = (idx & 31) * 4;
            cp_async16(sa(Ks + row * AKS + c4),
                       Kb + (size_t)(k0 + row) * QKVW + c4);
        }
#pragma unroll
        for (int it = 0; it < 8; it++) {
            int idx = it * 256 + tid;
            int row = idx >> 4;              // dim 0..127
            int c4  = (idx & 15) * 4;        // key offset 0..60
            cp_async16(sa(Vs + row * AVT + c4),
                       Vg + (size_t)row * SEQ + k0 + c4);
        }
        cp_commit();
    };

    load_kv(0, 0);
    load_kv(1, 1);

    // per-lane ldmatrix base offsets (bytes, relative)
    const uint32_t kboff = (uint32_t)((((lm >> 1) * 8 + lr) * AKS + (lm & 1) * 4) * 4);
    const uint32_t vboff = (uint32_t)((((lm >> 1) * 8 + lr) * AVT + (lm & 1) * 4) * 4);
    const uint32_t paoff = sa(sm + PS_OFF) +
        (uint32_t)(((wid * 16 + (lm & 1) * 8 + lr) * APS + (lm >> 1) * 4) * 4);

    for (int kt = 0; kt < nkt; kt++) {
        const int st = kt & 1;
        const int k0 = kt * 64;
        if (kt + 1 < nkt) cp_wait<1>();
        else              cp_wait<0>();
        __syncthreads();

        const uint32_t Ks = sa(sm + st * STG_FLOATS);
        const uint32_t Vs = Ks + KS_FLOATS * 4;

        // ---- scores S = Q K^T ----
        float sc[8][4];
#pragma unroll
        for (int ni = 0; ni < 8; ni++)
#pragma unroll
            for (int r = 0; r < 4; r++) sc[ni][r] = 0.0f;

#pragma unroll
        for (int kk = 0; kk < 16; kk++) {
            uint32_t bfr[8][2];
#pragma unroll
            for (int p = 0; p < 4; p++)
                ldsm4(bfr[2*p][0], bfr[2*p][1], bfr[2*p+1][0], bfr[2*p+1][1],
                      Ks + kboff + (uint32_t)((p * 16 * AKS + kk * 8) * 4));
#pragma unroll
            for (int ni = 0; ni < 8; ni++)
                mma_tf32(sc[ni], qa[kk], bfr[ni]);
        }

        // ---- causal mask ----
        if (k0 + 63 > qbase) {
#pragma unroll
            for (int ni = 0; ni < 8; ni++) {
                int c0 = k0 + ni * 8 + 2 * t;
                int r0 = qbase + g;
                if (c0 > r0)     sc[ni][0] = -1e30f;
                if (c0 + 1 > r0) sc[ni][1] = -1e30f;
                if (c0 > r0 + 8)     sc[ni][2] = -1e30f;
                if (c0 + 1 > r0 + 8) sc[ni][3] = -1e30f;
            }
        }

        // ---- online softmax ----
        float mx0 = -1e30f, mx1 = -1e30f;
#pragma unroll
        for (int ni = 0; ni < 8; ni++) {
            mx0 = fmaxf(mx0, fmaxf(sc[ni][0], sc[ni][1]));
            mx1 = fmaxf(mx1, fmaxf(sc[ni][2], sc[ni][3]));
        }
        mx0 = fmaxf(mx0, __shfl_xor_sync(0xffffffffu, mx0, 1));
        mx0 = fmaxf(mx0, __shfl_xor_sync(0xffffffffu, mx0, 2));
        mx1 = fmaxf(mx1, __shfl_xor_sync(0xffffffffu, mx1, 1));
        mx1 = fmaxf(mx1, __shfl_xor_sync(0xffffffffu, mx1, 2));

        float mn0 = fmaxf(m0r, mx0);
        float mn1 = fmaxf(m1r, mx1);
        float cr0 = ex2(m0r - mn0);
        float cr1 = ex2(m1r - mn1);
        m0r = mn0; m1r = mn1;

        float rs0 = 0.0f, rs1 = 0.0f;
        float* pw0 = sm + PS_OFF + (wid * 16 + g) * APS;
        float* pw1 = pw0 + 8 * APS;
#pragma unroll
        for (int ni = 0; ni < 8; ni++) {
            float p0 = ex2(sc[ni][0] - mn0);
            float p1 = ex2(sc[ni][1] - mn0);
            float p2 = ex2(sc[ni][2] - mn1);
            float p3 = ex2(sc[ni][3] - mn1);
            rs0 += p0 + p1;
            rs1 += p2 + p3;
            *(float2*)(pw0 + ni * 8 + 2 * t) = make_float2(tf32rn(p0), tf32rn(p1));
            *(float2*)(pw1 + ni * 8 + 2 * t) = make_float2(tf32rn(p2), tf32rn(p3));
        }
        rs0 += __shfl_xor_sync(0xffffffffu, rs0, 1);
        rs0 += __shfl_xor_sync(0xffffffffu, rs0, 2);
        rs1 += __shfl_xor_sync(0xffffffffu, rs1, 1);
        rs1 += __shfl_xor_sync(0xffffffffu, rs1, 2);
        l0r = l0r * cr0 + rs0;
        l1r = l1r * cr1 + rs1;

#pragma unroll
        for (int ni = 0; ni < 16; ni++) {
            oa[ni][0] *= cr0; oa[ni][1] *= cr0;
            oa[ni][2] *= cr1; oa[ni][3] *= cr1;
        }
        __syncwarp();

        // ---- O += P V : P A-frags + V (dim-major) B-frags via ldmatrix ----
#pragma unroll
        for (int kk = 0; kk < 8; kk++) {
            uint32_t a[4];
            ldsm4(a[0], a[1], a[2], a[3], paoff + kk * 32);
#pragma unroll
            for (int p = 0; p < 8; p++) {
                uint32_t bfr0[2], bfr1[2];
                ldsm4(bfr0[0], bfr0[1], bfr1[0], bfr1[1],
                      Vs + vboff + (uint32_t)((p * 16 * AVT + kk * 8) * 4));
                mma_tf32(oa[2*p],     a, bfr0);
                mma_tf32(oa[2*p + 1], a, bfr1);
            }
        }
        __syncthreads();
        if (kt + 2 < nkt) load_kv(kt + 2, st);
    }

    // ---- epilogue: O / l, tf32-rounded for the O-projection ----
    float inv0 = 1.0f / l0r;
    float inv1 = 1.0f / l1r;
    float* o0 = O + (size_t)((size_t)b * SEQ + qbase + g) * QROW + h * HD;
    float* o1 = o0 + (size_t)8 * QROW;
#pragma unroll
    for (int ni = 0; ni < 16; ni++) {
        *(float2*)(o0 + ni * 8 + 2 * t) =
            make_float2(tf32rn(oa[ni][0] * inv0), tf32rn(oa[ni][1] * inv0));
        *(float2*)(o1 + ni * 8 + 2 * t) =
            make_float2(tf32rn(oa[ni][2] * inv1), tf32rn(oa[ni][3] * inv1));
    }
}

// =================================================================
extern "C" void kernel_launch(void* const* d_in, const int* in_sizes, int n_in,
                              void* d_out, int out_size)
{
    const float* hs   = (const float*)d_in[0];
    const float* cosb = (const float*)d_in[1];
    const float* sinb = (const float*)d_in[2];
    const float* wq   = (const float*)d_in[3];
    const float* wk   = (const float*)d_in[4];
    const float* wv   = (const float*)d_in[5];
    const float* wo   = (const float*)d_in[6];
    float* out = (float*)d_out;

    float *qkv, *vt, *attn, *hsc, *wqkv, *woc;
    cudaGetSymbolAddress((void**)&qkv,  g_qkv);
    cudaGetSymbolAddress((void**)&vt,   g_vt);
    cudaGetSymbolAddress((void**)&attn, g_attn);
    cudaGetSymbolAddress((void**)&hsc,  g_hsc);
    cudaGetSymbolAddress((void**)&wqkv, g_wqkv);
    cudaGetSymbolAddress((void**)&woc,  g_woc);

    cudaFuncSetAttribute(gemm_mma, cudaFuncAttributeMaxDynamicSharedMemorySize, GEMM_SMEM);
    cudaFuncSetAttribute(attn_mma, cudaFuncAttributeMaxDynamicSharedMemorySize, ATTN_SMEM);

    // L0: fused tf32 rounding (hs + wq|wk|wv + wo), 4 float4 per thread
    long nblk = (NALL4 + 1023) / 1024;
    round_all_kernel<<<(unsigned)nblk, 256>>>(
        (const float4*)hs, (const float4*)wq, (const float4*)wk,
        (const float4*)wv, (const float4*)wo,
        (float4*)hsc, (float4*)wqkv, (float4*)woc);

    // L1: fused QKV projection; V columns written dim-major into g_vt
    gemm_mma<<<dim3(QKVW / 256, TOKENS / 128), 256, GEMM_SMEM>>>(
        hsc, wqkv, qkv, TOKENS, QKVW, HID, vt);

    // L2: fused RoPE Q+K (Q scale folds 1/sqrt(128)*log2(e))
    const float qscale = 0.08838834764831845f * 1.4426950408889634f;
    rope_qk_kernel<<<(TOKENS * (NH + NKV) * 64) / 256, 256>>>(qkv, cosb, sinb, qscale);

    // L3: flash attention  (profiled: launch index 3)
    attn_mma<<<dim3(SEQ / 128, BATCH * NH), 256, ATTN_SMEM>>>(qkv, vt, attn);

    // L4: output projection
    gemm_mma<<<dim3(HID / 256, TOKENS / 128), 256, GEMM_SMEM>>>(
        attn, woc, out, TOKENS, HID, QROW, nullptr);
}